// round 14
// baseline (speedup 1.0000x reference)
#include <cuda_runtime.h>

#define NN 384
#define DD 128
#define MARGIN_F 0.2f
#define APB 4
#define NBLK (NN / APB)       // 96 blocks -> single wave
#define NTHR 768              // 24 warps, 6 per SMSP
#define MAXPOS 64
#define NWARP 24
#define TROW 33               // padded float4 row stride
#define TSMEM (NN * TROW * 16)  // 202752 B

typedef unsigned long long u64;

// packed 2xf32 FMA (sm_103a f32x2 pipe; ptxas never emits this from C++)
__device__ __forceinline__ u64 ffma2(u64 a, u64 b, u64 c) {
    u64 d;
    asm("fma.rn.f32x2 %0, %1, %2, %3;" : "=l"(d) : "l"(a), "l"(b), "l"(c));
    return d;
}
__device__ __forceinline__ float unpack_sum(u64 p) {
    float lo, hi;
    asm("mov.b64 {%0, %1}, %2;" : "=f"(lo), "=f"(hi) : "l"(p));
    return lo + hi;
}

// Scratch (no allocations allowed)
__device__ float g_total;
__device__ float g_count;
__device__ unsigned int g_ctr;

__global__ void __launch_bounds__(NTHR) fused_k(
    const float* __restrict__ feat,
    const int*   __restrict__ y,
    float*       __restrict__ out)
{
    extern __shared__ float4 T4[];    // [row][c] padded, 384 x 33
    const int t = threadIdx.x;
    const int ab = blockIdx.x * APB;
    const int h = t / NN;             // k-half
    const int j = t - h * NN;         // column
    const int w = t >> 5, lane = t & 31;
    const unsigned FULL = 0xFFFFFFFFu;

    __shared__ float4 fa4[APB][DD / 4];   // anchor rows (uniform reads)
    __shared__ float part[2][APB][NN];
    __shared__ float rrp[2][NN];
    __shared__ float ras[APB];
    __shared__ int   yas[APB];
    __shared__ float pos_d[APB][MAXPOS];
    __shared__ int   wc[APB][12];
    __shared__ int   wbase[APB][12];
    __shared__ int   np_s[APB];
    __shared__ float red_f[NWARP];

    // ---- stage ALL of feat into padded smem + anchor rows ----
    const float4* feat4 = reinterpret_cast<const float4*>(feat);
#pragma unroll
    for (int rep = 0; rep < 2; rep++) {
        float4 pre[8];
#pragma unroll
        for (int i = 0; i < 8; i++)
            pre[i] = feat4[(rep * 8 + i) * NTHR + t];
#pragma unroll
        for (int i = 0; i < 8; i++) {
            const int f = (rep * 8 + i) * NTHR + t;
            T4[(f >> 5) * TROW + (f & 31)] = pre[i];
        }
    }
    if (t < APB * (DD / 4)) {
        const int m = t >> 5, k4 = t & 31;
        fa4[m][k4] = feat4[(ab + m) * (DD / 4) + k4];
    }
    if (t < APB) yas[t] = y[ab + t];
    const int yj = __ldg(&y[j]);
    __syncthreads();

    // ---- dot phase (packed f32x2): half h covers c = h*16 .. h*16+15 ----
    {
        u64 p0 = 0ull, p1 = 0ull, p2 = 0ull, p3 = 0ull, pr = 0ull;
        const ulonglong2* vr = reinterpret_cast<const ulonglong2*>(&T4[j * TROW + h * 16]);
        const ulonglong2* A0 = reinterpret_cast<const ulonglong2*>(&fa4[0][h * 16]);
        const ulonglong2* A1 = reinterpret_cast<const ulonglong2*>(&fa4[1][h * 16]);
        const ulonglong2* A2 = reinterpret_cast<const ulonglong2*>(&fa4[2][h * 16]);
        const ulonglong2* A3 = reinterpret_cast<const ulonglong2*>(&fa4[3][h * 16]);
#pragma unroll
        for (int kk = 0; kk < 16; kk++) {
            const ulonglong2 v = vr[kk];
            ulonglong2 a;
            a = A0[kk]; p0 = ffma2(a.x, v.x, p0); p0 = ffma2(a.y, v.y, p0);
            a = A1[kk]; p1 = ffma2(a.x, v.x, p1); p1 = ffma2(a.y, v.y, p1);
            a = A2[kk]; p2 = ffma2(a.x, v.x, p2); p2 = ffma2(a.y, v.y, p2);
            a = A3[kk]; p3 = ffma2(a.x, v.x, p3); p3 = ffma2(a.y, v.y, p3);
            pr = ffma2(v.x, v.x, pr); pr = ffma2(v.y, v.y, pr);
        }
        part[h][0][j] = unpack_sum(p0);
        part[h][1][j] = unpack_sum(p1);
        part[h][2][j] = unpack_sum(p2);
        part[h][3][j] = unpack_sum(p3);
        rrp[h][j] = unpack_sum(pr);
    }
    __syncthreads();

    // ---- combine partials; publish anchor norms ----
    float dts[APB], rr2;
#pragma unroll
    for (int m = 0; m < APB; m++)
        dts[m] = part[0][m][j] + part[1][m][j];
    rr2 = rrp[0][j] + rrp[1][j];
    if (h == 0 && (unsigned)(j - ab) < APB) ras[j - ab] = rr2;
    __syncthreads();

    // ---- d2 + ballot compaction (warps 0..11 carry columns uniquely) ----
    float d2[APB];
    bool  isp[APB];
#pragma unroll
    for (int m = 0; m < APB; m++) {
        d2[m] = fmaxf(ras[m] + rr2 - 2.0f * dts[m], 0.0f);
        isp[m] = (yj == yas[m]) && (j != ab + m);
    }
    unsigned pm[APB];
    if (w < 12) {
#pragma unroll
        for (int m = 0; m < APB; m++) {
            pm[m] = __ballot_sync(FULL, isp[m]);
            if (lane == 0) wc[m][w] = __popc(pm[m]);
        }
    }
    __syncthreads();
    if (t < APB) {
        int s = 0;
#pragma unroll
        for (int ww = 0; ww < 12; ww++) { wbase[t][ww] = s; s += wc[t][ww]; }
        np_s[t] = s;
    }
    __syncthreads();
    if (w < 12) {
#pragma unroll
        for (int m = 0; m < APB; m++) {
            if (isp[m]) {
                const int idx = wbase[m][w] + __popc(pm[m] & ((1u << lane) - 1u));
                pos_d[m][idx] = d2[m] + MARGIN_F;
            }
        }
    }
    __syncthreads();

    // ---- triplet sums: i-loop split across halves ----
    float acc = 0.0f;
#pragma unroll
    for (int m = 0; m < APB; m++) {
        const int npm = np_s[m];
        if (yj != yas[m]) {
            const float dn = d2[m];
            for (int i = h; i < npm; i += 2) {
                const float v = pos_d[m][i] - dn;
                acc += (v > 0.0f) ? v : 0.0f;
            }
        }
    }

    // ---- reduce + global accumulate + last-block finalize ----
#pragma unroll
    for (int off = 16; off > 0; off >>= 1)
        acc += __shfl_down_sync(FULL, acc, off);
    if (lane == 0) red_f[w] = acc;
    __syncthreads();
    if (w == 0) {
        float af = (lane < NWARP) ? red_f[lane] : 0.0f;
#pragma unroll
        for (int off = 16; off > 0; off >>= 1)
            af += __shfl_down_sync(FULL, af, off);
        if (lane == 0) {
            int cnt = 0;
#pragma unroll
            for (int m = 0; m < APB; m++)
                cnt += np_s[m] * (NN - 1 - np_s[m]);
            atomicAdd(&g_total, af);
            atomicAdd(&g_count, (float)cnt);
            __threadfence();
            const unsigned done = atomicAdd(&g_ctr, 1u);
            if (done == NBLK - 1) {
                const float tot = atomicAdd(&g_total, 0.0f);
                const float cn  = atomicAdd(&g_count, 0.0f);
                out[0] = tot / cn;
                g_total = 0.0f;
                g_count = 0.0f;
                g_ctr   = 0u;
            }
        }
    }
}

extern "C" void kernel_launch(void* const* d_in, const int* in_sizes, int n_in,
                              void* d_out, int out_size) {
    const float* feat = (const float*)d_in[0];
    // d_in[1] = logits (unused by the loss)
    const int*   yv   = (const int*)d_in[2];
    float* out = (float*)d_out;

    static int attr_set = 0;
    if (!attr_set) {
        cudaFuncSetAttribute(fused_k, cudaFuncAttributeMaxDynamicSharedMemorySize,
                             TSMEM);
        attr_set = 1;
    }
    fused_k<<<NBLK, NTHR, TSMEM>>>(feat, yv, out);
}